// round 2
// baseline (speedup 1.0000x reference)
#include <cuda_runtime.h>
#include <math.h>

// Problem constants
#define TTOK 200704          // B*H*W = 64*56*56 tokens
// C = 128, QKD = 128, HID = 512, NH = 4, HD = 32, WS = 7, N = 49, NW = 64

// ---------------- scratch (device globals; no allocation allowed) ----------
__device__ float g_xw  [(size_t)TTOK * 128];   // LN1'd, shifted, window-partitioned
__device__ float g_qkv [(size_t)TTOK * 384];   // qkv projection (windowed order)
__device__ float g_att [(size_t)TTOK * 128];   // attention output (windowed order)
__device__ float g_xres[(size_t)TTOK * 128];   // x + proj (natural order)
__device__ float g_mlp [(size_t)TTOK * 512];   // fc1+gelu output

__device__ __forceinline__ float warp_sum(float v) {
#pragma unroll
    for (int o = 16; o; o >>= 1) v += __shfl_xor_sync(0xffffffffu, v, o);
    return v;
}
__device__ __forceinline__ float warp_max(float v) {
#pragma unroll
    for (int o = 16; o; o >>= 1) v = fmaxf(v, __shfl_xor_sync(0xffffffffu, v, o));
    return v;
}

// ---------------- LayerNorm (warp per token). GATHER=true fuses
// roll(-3,-3) + window partition into the source index. -------------------
template <bool GATHER>
__global__ void ln_kernel(const float* __restrict__ x, const float* __restrict__ g,
                          const float* __restrict__ b, float* __restrict__ out) {
    int gt = blockIdx.x * blockDim.x + threadIdx.x;
    int tok = gt >> 5, lane = gt & 31;
    if (tok >= TTOK) return;
    size_t src;
    if (GATHER) {
        int win = tok / 49, n = tok - win * 49;
        int bb = win >> 6, wrem = win & 63;
        int ny = n / 7, nx = n - ny * 7;
        int gh = (wrem >> 3) * 7 + ny;
        int gw = (wrem & 7) * 7 + nx;
        int sh = gh + 3; if (sh >= 56) sh -= 56;
        int sw = gw + 3; if (sw >= 56) sw -= 56;
        src = (size_t)bb * 3136 + sh * 56 + sw;
    } else {
        src = (size_t)tok;
    }
    float4 v = ((const float4*)(x + src * 128))[lane];
    float mu = warp_sum(v.x + v.y + v.z + v.w) * (1.0f / 128.0f);
    float dx = v.x - mu, dy = v.y - mu, dz = v.z - mu, dw = v.w - mu;
    float var = warp_sum(dx * dx + dy * dy + dz * dz + dw * dw) * (1.0f / 128.0f);
    float inv = rsqrtf(var + 1e-5f);
    float4 gg = ((const float4*)g)[lane];
    float4 bv = ((const float4*)b)[lane];
    float4 o;
    o.x = dx * inv * gg.x + bv.x;
    o.y = dy * inv * gg.y + bv.y;
    o.z = dz * inv * gg.z + bv.z;
    o.w = dw * inv * gg.w + bv.w;
    ((float4*)out)[(size_t)tok * 32 + lane] = o;
}

// Map natural-order output token -> windowed-order attention row
// (window reverse + roll(+3,+3) fused into proj GEMM A-gather).
__device__ __forceinline__ size_t proj_gather(size_t m) {
    int bb = (int)(m / 3136);
    int r  = (int)(m - (size_t)bb * 3136);
    int h = r / 56, w = r - h * 56;
    int gh = h + 53; if (gh >= 56) gh -= 56;
    int gw = w + 53; if (gw >= 56) gw -= 56;
    int win = bb * 64 + (gh / 7) * 8 + (gw / 7);
    int n = (gh % 7) * 7 + (gw % 7);
    return (size_t)win * 49 + n;
}

// ---------------- SGEMM: C[M,N] = A[M,K] @ Bw[N,K]^T + bias, epilogue -----
// EPI: 0 = bias; 1 = bias + exact GELU; 2 = bias + residual add
// BM = BN = 128, BK = 8, 256 threads, 8x8 per-thread tile.
// Requires M%128==0, N%128==0, K%8==0 (all shapes here satisfy this).
template <int EPI, bool GATHER>
__global__ void __launch_bounds__(256, 2)
sgemm(const float* __restrict__ A, const float* __restrict__ Bw,
      const float* __restrict__ bias, const float* __restrict__ res,
      float* __restrict__ Cout, int M, int N, int K) {
    __shared__ float As[8][136];
    __shared__ float Bs[8][136];
    int t = threadIdx.x;
    int bm = blockIdx.y << 7;
    int bn = blockIdx.x << 7;
    int tx = t & 15, ty = t >> 4;
    int lr = t >> 1;            // 0..127: tile row loaded by this thread
    int lc = (t & 1) * 4;       // 0 or 4: k-offset within BK

    size_t arow = (size_t)(bm + lr);
    if (GATHER) arow = proj_gather(arow);
    const float* Ap = A + arow * (size_t)K + lc;
    const float* Bp = Bw + (size_t)(bn + lr) * K + lc;

    float acc[8][8];
#pragma unroll
    for (int i = 0; i < 8; i++)
#pragma unroll
        for (int j = 0; j < 8; j++) acc[i][j] = 0.0f;

    for (int k0 = 0; k0 < K; k0 += 8) {
        float4 av = *(const float4*)(Ap + k0);
        float4 bv = *(const float4*)(Bp + k0);
        __syncthreads();
        As[lc + 0][lr] = av.x; As[lc + 1][lr] = av.y;
        As[lc + 2][lr] = av.z; As[lc + 3][lr] = av.w;
        Bs[lc + 0][lr] = bv.x; Bs[lc + 1][lr] = bv.y;
        Bs[lc + 2][lr] = bv.z; Bs[lc + 3][lr] = bv.w;
        __syncthreads();
#pragma unroll
        for (int k = 0; k < 8; k++) {
            float a[8], bb[8];
            *(float4*)&a[0]  = *(const float4*)&As[k][ty * 8];
            *(float4*)&a[4]  = *(const float4*)&As[k][ty * 8 + 4];
            *(float4*)&bb[0] = *(const float4*)&Bs[k][tx * 8];
            *(float4*)&bb[4] = *(const float4*)&Bs[k][tx * 8 + 4];
#pragma unroll
            for (int i = 0; i < 8; i++)
#pragma unroll
                for (int j = 0; j < 8; j++)
                    acc[i][j] = fmaf(a[i], bb[j], acc[i][j]);
        }
    }

#pragma unroll
    for (int i = 0; i < 8; i++) {
        size_t m = (size_t)(bm + ty * 8 + i);
        float* crow = Cout + m * (size_t)N + bn + tx * 8;
        const float* rrow = (EPI == 2) ? (res + m * (size_t)N + bn + tx * 8) : (const float*)0;
#pragma unroll
        for (int j = 0; j < 8; j++) {
            float v = acc[i][j] + bias[bn + tx * 8 + j];
            if (EPI == 1) v = 0.5f * v * (1.0f + erff(v * 0.70710678118654752f));
            if (EPI == 2) v += rrow[j];
            crow[j] = v;
        }
    }
}

// ---------------- Windowed attention: one block per (window, head) --------
// q,k,v: 49x32 tiles in smem (stride 33). Relative-position bias and the
// Swin shift-region mask are computed inline (no tables).
__global__ void __launch_bounds__(128)
attn_kernel(const float* __restrict__ qkv, const float* __restrict__ rpb,
            float* __restrict__ out) {
    __shared__ float qs[49 * 33];
    __shared__ float ks[49 * 33];
    __shared__ float vs[49 * 33];
    __shared__ float S[49 * 50];
    __shared__ int reg[49];

    int win = blockIdx.x >> 2;
    int head = blockIdx.x & 3;
    int t = threadIdx.x;
    int lane = t & 31, wid = t >> 5;

    int wrem = win & 63;
    int wh = wrem >> 3, ww = wrem & 7;
    if (t < 49) {
        int y = t / 7, xx = t - y * 7;
        int gh = wh * 7 + y, gw = ww * 7 + xx;
        int rh = gh < 49 ? 0 : (gh < 53 ? 1 : 2);
        int rw = gw < 49 ? 0 : (gw < 53 ? 1 : 2);
        reg[t] = rh * 3 + rw;
    }

    size_t base = (size_t)win * 49 * 384 + head * 32;
    const float SCALE = 0.17677669529663687f;  // 32^-0.5
    for (int nn = wid; nn < 49; nn += 4) {
        size_t rb = base + (size_t)nn * 384;
        qs[nn * 33 + lane] = qkv[rb + lane] * SCALE;
        ks[nn * 33 + lane] = qkv[rb + 128 + lane];
        vs[nn * 33 + lane] = qkv[rb + 256 + lane];
    }
    __syncthreads();

    for (int idx = t; idx < 2401; idx += 128) {
        int n = idx / 49, m = idx - n * 49;
        const float* qr = &qs[n * 33];
        const float* kr = &ks[m * 33];
        float s = 0.0f;
#pragma unroll
        for (int d = 0; d < 32; d++) s = fmaf(qr[d], kr[d], s);
        int y1 = n / 7, x1 = n - y1 * 7;
        int y2 = m / 7, x2 = m - y2 * 7;
        int rpi = (y1 - y2 + 6) * 13 + (x1 - x2 + 6);
        s += rpb[rpi * 4 + head];
        if (reg[n] != reg[m]) s -= 100.0f;
        S[n * 50 + m] = s;
    }
    __syncthreads();

    for (int n = wid; n < 49; n += 4) {
        float* row = &S[n * 50];
        float v0 = row[lane];
        float v1 = (lane + 32 < 49) ? row[lane + 32] : -1e30f;
        float mx = warp_max(fmaxf(v0, v1));
        float e0 = __expf(v0 - mx);
        float e1 = (lane + 32 < 49) ? __expf(v1 - mx) : 0.0f;
        float inv = 1.0f / warp_sum(e0 + e1);
        row[lane] = e0 * inv;
        if (lane + 32 < 49) row[lane + 32] = e1 * inv;
    }
    __syncthreads();

    int d = lane;
    for (int n = wid; n < 49; n += 4) {
        float o = 0.0f;
        const float* prow = &S[n * 50];
#pragma unroll 7
        for (int m = 0; m < 49; m++) o = fmaf(prow[m], vs[m * 33 + d], o);
        out[((size_t)win * 49 + n) * 128 + head * 32 + d] = o;
    }
}

// ---------------- launch ---------------------------------------------------
extern "C" void kernel_launch(void* const* d_in, const int* in_sizes, int n_in,
                              void* d_out, int out_size) {
    const float* x      = (const float*)d_in[0];
    const float* ln1_g  = (const float*)d_in[1];
    const float* ln1_b  = (const float*)d_in[2];
    const float* qkv_w  = (const float*)d_in[3];
    const float* qkv_b  = (const float*)d_in[4];
    const float* rpb    = (const float*)d_in[5];
    const float* proj_w = (const float*)d_in[6];
    const float* proj_b = (const float*)d_in[7];
    const float* ln2_g  = (const float*)d_in[8];
    const float* ln2_b  = (const float*)d_in[9];
    const float* fc1_w  = (const float*)d_in[10];
    const float* fc1_b  = (const float*)d_in[11];
    const float* fc2_w  = (const float*)d_in[12];
    const float* fc2_b  = (const float*)d_in[13];
    float* out = (float*)d_out;

    void* p;
    cudaGetSymbolAddress(&p, g_xw);   float* xw   = (float*)p;
    cudaGetSymbolAddress(&p, g_qkv);  float* qkvb = (float*)p;
    cudaGetSymbolAddress(&p, g_att);  float* att  = (float*)p;
    cudaGetSymbolAddress(&p, g_xres); float* xres = (float*)p;
    cudaGetSymbolAddress(&p, g_mlp);  float* mlp  = (float*)p;

    const int LN_BLOCKS = (TTOK * 32) / 256;  // 25088

    // 1. LN1 + shift + window partition
    ln_kernel<true><<<LN_BLOCKS, 256>>>(x, ln1_g, ln1_b, xw);
    // 2. QKV projection: (T,128) @ (384,128)^T
    sgemm<0, false><<<dim3(3, 1568), 256>>>(xw, qkv_w, qkv_b, nullptr, qkvb,
                                            TTOK, 384, 128);
    // 3. Windowed attention, one block per (window, head)
    attn_kernel<<<16384, 128>>>(qkvb, rpb, att);
    // 4. proj + window-reverse + unshift (A gather) + residual
    sgemm<2, true><<<dim3(1, 1568), 256>>>(att, proj_w, proj_b, x, xres,
                                           TTOK, 128, 128);
    // 5. LN2
    ln_kernel<false><<<LN_BLOCKS, 256>>>(xres, ln2_g, ln2_b, xw);
    // 6. fc1 + exact GELU
    sgemm<1, false><<<dim3(4, 1568), 256>>>(xw, fc1_w, fc1_b, nullptr, mlp,
                                            TTOK, 512, 128);
    // 7. fc2 + residual -> output
    sgemm<2, false><<<dim3(1, 1568), 256>>>(mlp, fc2_w, fc2_b, xres, out,
                                            TTOK, 128, 512);
}

// round 7
// speedup vs baseline: 1.0016x; 1.0016x over previous
#include <cuda_runtime.h>
#include <math.h>

// Problem constants
#define TTOK 200704          // B*H*W = 64*56*56 tokens
// C = 128, QKD = 128, HID = 512, NH = 4, HD = 32, WS = 7, N = 49, NW = 64

// ---------------- scratch (device globals; no allocation allowed) ----------
__device__ float g_xw  [(size_t)TTOK * 128];   // LN1'd, shifted, window-partitioned
__device__ float g_qkv [(size_t)TTOK * 384];   // qkv projection (windowed order)
__device__ float g_att [(size_t)TTOK * 128];   // attention output (windowed order)
__device__ float g_xres[(size_t)TTOK * 128];   // x + proj (natural order)
__device__ float g_mlp [(size_t)TTOK * 512];   // fc1+gelu output

__device__ __forceinline__ float warp_sum(float v) {
#pragma unroll
    for (int o = 16; o; o >>= 1) v += __shfl_xor_sync(0xffffffffu, v, o);
    return v;
}
__device__ __forceinline__ float warp_max(float v) {
#pragma unroll
    for (int o = 16; o; o >>= 1) v = fmaxf(v, __shfl_xor_sync(0xffffffffu, v, o));
    return v;
}

// ---------------- LayerNorm (warp per token). GATHER=true fuses
// roll(-3,-3) + window partition into the source index. -------------------
template <bool GATHER>
__global__ void ln_kernel(const float* __restrict__ x, const float* __restrict__ g,
                          const float* __restrict__ b, float* __restrict__ out) {
    int gt = blockIdx.x * blockDim.x + threadIdx.x;
    int tok = gt >> 5, lane = gt & 31;
    if (tok >= TTOK) return;
    size_t src;
    if (GATHER) {
        int win = tok / 49, n = tok - win * 49;
        int bb = win >> 6, wrem = win & 63;
        int ny = n / 7, nx = n - ny * 7;
        int gh = (wrem >> 3) * 7 + ny;
        int gw = (wrem & 7) * 7 + nx;
        int sh = gh + 3; if (sh >= 56) sh -= 56;
        int sw = gw + 3; if (sw >= 56) sw -= 56;
        src = (size_t)bb * 3136 + sh * 56 + sw;
    } else {
        src = (size_t)tok;
    }
    float4 v = ((const float4*)(x + src * 128))[lane];
    float mu = warp_sum(v.x + v.y + v.z + v.w) * (1.0f / 128.0f);
    float dx = v.x - mu, dy = v.y - mu, dz = v.z - mu, dw = v.w - mu;
    float var = warp_sum(dx * dx + dy * dy + dz * dz + dw * dw) * (1.0f / 128.0f);
    float inv = rsqrtf(var + 1e-5f);
    float4 gg = ((const float4*)g)[lane];
    float4 bv = ((const float4*)b)[lane];
    float4 o;
    o.x = dx * inv * gg.x + bv.x;
    o.y = dy * inv * gg.y + bv.y;
    o.z = dz * inv * gg.z + bv.z;
    o.w = dw * inv * gg.w + bv.w;
    ((float4*)out)[(size_t)tok * 32 + lane] = o;
}

// Map natural-order output token -> windowed-order attention row
// (window reverse + roll(+3,+3) fused into proj GEMM A-gather).
__device__ __forceinline__ size_t proj_gather(size_t m) {
    int bb = (int)(m / 3136);
    int r  = (int)(m - (size_t)bb * 3136);
    int h = r / 56, w = r - h * 56;
    int gh = h + 53; if (gh >= 56) gh -= 56;
    int gw = w + 53; if (gw >= 56) gw -= 56;
    int win = bb * 64 + (gh / 7) * 8 + (gw / 7);
    int n = (gh % 7) * 7 + (gw % 7);
    return (size_t)win * 49 + n;
}

// ---------------- SGEMM: C[M,N] = A[M,K] @ Bw[N,K]^T + bias, epilogue -----
// EPI: 0 = bias; 1 = bias + exact GELU; 2 = bias + residual add
// BM = BN = 128, BK = 8, 256 threads, 8x8 per-thread tile.
// Requires M%128==0, N%128==0, K%8==0 (all shapes here satisfy this).
template <int EPI, bool GATHER>
__global__ void __launch_bounds__(256, 2)
sgemm(const float* __restrict__ A, const float* __restrict__ Bw,
      const float* __restrict__ bias, const float* __restrict__ res,
      float* __restrict__ Cout, int M, int N, int K) {
    __shared__ float As[8][136];
    __shared__ float Bs[8][136];
    int t = threadIdx.x;
    int bm = blockIdx.y << 7;
    int bn = blockIdx.x << 7;
    int tx = t & 15, ty = t >> 4;
    int lr = t >> 1;            // 0..127: tile row loaded by this thread
    int lc = (t & 1) * 4;       // 0 or 4: k-offset within BK

    size_t arow = (size_t)(bm + lr);
    if (GATHER) arow = proj_gather(arow);
    const float* Ap = A + arow * (size_t)K + lc;
    const float* Bp = Bw + (size_t)(bn + lr) * K + lc;

    float acc[8][8];
#pragma unroll
    for (int i = 0; i < 8; i++)
#pragma unroll
        for (int j = 0; j < 8; j++) acc[i][j] = 0.0f;

    for (int k0 = 0; k0 < K; k0 += 8) {
        float4 av = *(const float4*)(Ap + k0);
        float4 bv = *(const float4*)(Bp + k0);
        __syncthreads();
        As[lc + 0][lr] = av.x; As[lc + 1][lr] = av.y;
        As[lc + 2][lr] = av.z; As[lc + 3][lr] = av.w;
        Bs[lc + 0][lr] = bv.x; Bs[lc + 1][lr] = bv.y;
        Bs[lc + 2][lr] = bv.z; Bs[lc + 3][lr] = bv.w;
        __syncthreads();
#pragma unroll
        for (int k = 0; k < 8; k++) {
            float a[8], bb[8];
            *(float4*)&a[0]  = *(const float4*)&As[k][ty * 8];
            *(float4*)&a[4]  = *(const float4*)&As[k][ty * 8 + 4];
            *(float4*)&bb[0] = *(const float4*)&Bs[k][tx * 8];
            *(float4*)&bb[4] = *(const float4*)&Bs[k][tx * 8 + 4];
#pragma unroll
            for (int i = 0; i < 8; i++)
#pragma unroll
                for (int j = 0; j < 8; j++)
                    acc[i][j] = fmaf(a[i], bb[j], acc[i][j]);
        }
    }

#pragma unroll
    for (int i = 0; i < 8; i++) {
        size_t m = (size_t)(bm + ty * 8 + i);
        float* crow = Cout + m * (size_t)N + bn + tx * 8;
        const float* rrow = (EPI == 2) ? (res + m * (size_t)N + bn + tx * 8) : (const float*)0;
#pragma unroll
        for (int j = 0; j < 8; j++) {
            float v = acc[i][j] + bias[bn + tx * 8 + j];
            if (EPI == 1) v = 0.5f * v * (1.0f + erff(v * 0.70710678118654752f));
            if (EPI == 2) v += rrow[j];
            crow[j] = v;
        }
    }
}

// ---------------- Windowed attention: one block per (window, head) --------
// q,k,v: 49x32 tiles in smem (stride 33). Relative-position bias and the
// Swin shift-region mask are computed inline (no tables).
__global__ void __launch_bounds__(128)
attn_kernel(const float* __restrict__ qkv, const float* __restrict__ rpb,
            float* __restrict__ out) {
    __shared__ float qs[49 * 33];
    __shared__ float ks[49 * 33];
    __shared__ float vs[49 * 33];
    __shared__ float S[49 * 50];
    __shared__ int reg[49];

    int win = blockIdx.x >> 2;
    int head = blockIdx.x & 3;
    int t = threadIdx.x;
    int lane = t & 31, wid = t >> 5;

    int wrem = win & 63;
    int wh = wrem >> 3, ww = wrem & 7;
    if (t < 49) {
        int y = t / 7, xx = t - y * 7;
        int gh = wh * 7 + y, gw = ww * 7 + xx;
        int rh = gh < 49 ? 0 : (gh < 53 ? 1 : 2);
        int rw = gw < 49 ? 0 : (gw < 53 ? 1 : 2);
        reg[t] = rh * 3 + rw;
    }

    size_t base = (size_t)win * 49 * 384 + head * 32;
    const float SCALE = 0.17677669529663687f;  // 32^-0.5
    for (int nn = wid; nn < 49; nn += 4) {
        size_t rb = base + (size_t)nn * 384;
        qs[nn * 33 + lane] = qkv[rb + lane] * SCALE;
        ks[nn * 33 + lane] = qkv[rb + 128 + lane];
        vs[nn * 33 + lane] = qkv[rb + 256 + lane];
    }
    __syncthreads();

    for (int idx = t; idx < 2401; idx += 128) {
        int n = idx / 49, m = idx - n * 49;
        const float* qr = &qs[n * 33];
        const float* kr = &ks[m * 33];
        float s = 0.0f;
#pragma unroll
        for (int d = 0; d < 32; d++) s = fmaf(qr[d], kr[d], s);
        int y1 = n / 7, x1 = n - y1 * 7;
        int y2 = m / 7, x2 = m - y2 * 7;
        int rpi = (y1 - y2 + 6) * 13 + (x1 - x2 + 6);
        s += rpb[rpi * 4 + head];
        if (reg[n] != reg[m]) s -= 100.0f;
        S[n * 50 + m] = s;
    }
    __syncthreads();

    for (int n = wid; n < 49; n += 4) {
        float* row = &S[n * 50];
        float v0 = row[lane];
        float v1 = (lane + 32 < 49) ? row[lane + 32] : -1e30f;
        float mx = warp_max(fmaxf(v0, v1));
        float e0 = __expf(v0 - mx);
        float e1 = (lane + 32 < 49) ? __expf(v1 - mx) : 0.0f;
        float inv = 1.0f / warp_sum(e0 + e1);
        row[lane] = e0 * inv;
        if (lane + 32 < 49) row[lane + 32] = e1 * inv;
    }
    __syncthreads();

    int d = lane;
    for (int n = wid; n < 49; n += 4) {
        float o = 0.0f;
        const float* prow = &S[n * 50];
#pragma unroll 7
        for (int m = 0; m < 49; m++) o = fmaf(prow[m], vs[m * 33 + d], o);
        out[((size_t)win * 49 + n) * 128 + head * 32 + d] = o;
    }
}

// ---------------- launch ---------------------------------------------------
extern "C" void kernel_launch(void* const* d_in, const int* in_sizes, int n_in,
                              void* d_out, int out_size) {
    const float* x      = (const float*)d_in[0];
    const float* ln1_g  = (const float*)d_in[1];
    const float* ln1_b  = (const float*)d_in[2];
    const float* qkv_w  = (const float*)d_in[3];
    const float* qkv_b  = (const float*)d_in[4];
    const float* rpb    = (const float*)d_in[5];
    const float* proj_w = (const float*)d_in[6];
    const float* proj_b = (const float*)d_in[7];
    const float* ln2_g  = (const float*)d_in[8];
    const float* ln2_b  = (const float*)d_in[9];
    const float* fc1_w  = (const float*)d_in[10];
    const float* fc1_b  = (const float*)d_in[11];
    const float* fc2_w  = (const float*)d_in[12];
    const float* fc2_b  = (const float*)d_in[13];
    float* out = (float*)d_out;

    void* p;
    cudaGetSymbolAddress(&p, g_xw);   float* xw   = (float*)p;
    cudaGetSymbolAddress(&p, g_qkv);  float* qkvb = (float*)p;
    cudaGetSymbolAddress(&p, g_att);  float* att  = (float*)p;
    cudaGetSymbolAddress(&p, g_xres); float* xres = (float*)p;
    cudaGetSymbolAddress(&p, g_mlp);  float* mlp  = (float*)p;

    const int LN_BLOCKS = (TTOK * 32) / 256;  // 25088

    // 1. LN1 + shift + window partition
    ln_kernel<true><<<LN_BLOCKS, 256>>>(x, ln1_g, ln1_b, xw);
    // 2. QKV projection: (T,128) @ (384,128)^T
    sgemm<0, false><<<dim3(3, 1568), 256>>>(xw, qkv_w, qkv_b, nullptr, qkvb,
                                            TTOK, 384, 128);
    // 3. Windowed attention, one block per (window, head)
    attn_kernel<<<16384, 128>>>(qkvb, rpb, att);
    // 4. proj + window-reverse + unshift (A gather) + residual
    sgemm<2, true><<<dim3(1, 1568), 256>>>(att, proj_w, proj_b, x, xres,
                                           TTOK, 128, 128);
    // 5. LN2
    ln_kernel<false><<<LN_BLOCKS, 256>>>(xres, ln2_g, ln2_b, xw);
    // 6. fc1 + exact GELU
    sgemm<1, false><<<dim3(4, 1568), 256>>>(xw, fc1_w, fc1_b, nullptr, mlp,
                                            TTOK, 512, 128);
    // 7. fc2 + residual -> output
    sgemm<2, false><<<dim3(1, 1568), 256>>>(mlp, fc2_w, fc2_b, xres, out,
                                            TTOK, 128, 512);
}

// round 11
// speedup vs baseline: 2.4561x; 2.4522x over previous
#include <cuda_runtime.h>
#include <cuda_bf16.h>
#include <math.h>
#include <stdint.h>

#define TTOK 200704          // B*H*W = 64*56*56 tokens
// C=128, QKD=128, HID=512, NH=4, HD=32, WS=7, N=49, NW=64

// ---------------- scratch (device globals; no allocation allowed) ----------
__device__ __nv_bfloat16 g_xw [(size_t)TTOK * 128];   // LN output (bf16)
__device__ __nv_bfloat16 g_qkv[(size_t)TTOK * 384];   // qkv (windowed, bf16)
__device__ __nv_bfloat16 g_att[(size_t)TTOK * 128];   // attn out (windowed, bf16)
__device__ float         g_xres[(size_t)TTOK * 128];  // x + proj (natural, fp32)
__device__ __nv_bfloat16 g_mlp[(size_t)TTOK * 512];   // gelu(fc1) (bf16)
__device__ __nv_bfloat16 g_wq[384 * 128];
__device__ __nv_bfloat16 g_wp[128 * 128];
__device__ __nv_bfloat16 g_w1[512 * 128];
__device__ __nv_bfloat16 g_w2[128 * 512];

__device__ __forceinline__ uint32_t smem_u32(const void* p) {
    return (uint32_t)__cvta_generic_to_shared(p);
}
__device__ __forceinline__ float warp_sum(float v) {
#pragma unroll
    for (int o = 16; o; o >>= 1) v += __shfl_xor_sync(0xffffffffu, v, o);
    return v;
}
__device__ __forceinline__ float warp_max(float v) {
#pragma unroll
    for (int o = 16; o; o >>= 1) v = fmaxf(v, __shfl_xor_sync(0xffffffffu, v, o));
    return v;
}

// ---------------- fp32 -> bf16 weight conversion ---------------------------
__global__ void f2bf(const float* __restrict__ s, __nv_bfloat16* __restrict__ d, int n) {
    int i = (blockIdx.x * blockDim.x + threadIdx.x) * 4;
    if (i < n) {
        float4 v = *(const float4*)(s + i);
        __nv_bfloat162* dp = (__nv_bfloat162*)(d + i);
        dp[0] = __floats2bfloat162_rn(v.x, v.y);
        dp[1] = __floats2bfloat162_rn(v.z, v.w);
    }
}

// ---------------- LayerNorm (warp/token), bf16 out. GATHER fuses
// roll(-3,-3) + window partition into the source index. ---------------------
template <bool GATHER>
__global__ void ln_kernel(const float* __restrict__ x, const float* __restrict__ g,
                          const float* __restrict__ b, __nv_bfloat16* __restrict__ out) {
    int gt = blockIdx.x * blockDim.x + threadIdx.x;
    int tok = gt >> 5, lane = gt & 31;
    if (tok >= TTOK) return;
    size_t src;
    if (GATHER) {
        int win = tok / 49, n = tok - win * 49;
        int bb = win >> 6, wrem = win & 63;
        int ny = n / 7, nx = n - ny * 7;
        int gh = (wrem >> 3) * 7 + ny;
        int gw = (wrem & 7) * 7 + nx;
        int sh = gh + 3; if (sh >= 56) sh -= 56;
        int sw = gw + 3; if (sw >= 56) sw -= 56;
        src = (size_t)bb * 3136 + sh * 56 + sw;
    } else {
        src = (size_t)tok;
    }
    float4 v = ((const float4*)(x + src * 128))[lane];
    float mu = warp_sum(v.x + v.y + v.z + v.w) * (1.0f / 128.0f);
    float dx = v.x - mu, dy = v.y - mu, dz = v.z - mu, dw = v.w - mu;
    float var = warp_sum(dx * dx + dy * dy + dz * dz + dw * dw) * (1.0f / 128.0f);
    float inv = rsqrtf(var + 1e-5f);
    float4 gg = ((const float4*)g)[lane];
    float4 bv = ((const float4*)b)[lane];
    __nv_bfloat162* op = (__nv_bfloat162*)(out + (size_t)tok * 128);
    op[lane * 2]     = __floats2bfloat162_rn(dx * inv * gg.x + bv.x, dy * inv * gg.y + bv.y);
    op[lane * 2 + 1] = __floats2bfloat162_rn(dz * inv * gg.z + bv.z, dw * inv * gg.w + bv.w);
}

// natural-order output row -> windowed-order attention row
__device__ __forceinline__ size_t proj_gather(size_t m) {
    int bb = (int)(m / 3136);
    int r  = (int)(m - (size_t)bb * 3136);
    int h = r / 56, w = r - h * 56;
    int gh = h + 53; if (gh >= 56) gh -= 56;
    int gw = w + 53; if (gw >= 56) gw -= 56;
    int win = bb * 64 + (gh / 7) * 8 + (gw / 7);
    int n = (gh % 7) * 7 + (gw % 7);
    return (size_t)win * 49 + n;
}

// ---------------- bf16 HMMA GEMM: C[M,N] = A[M,K] @ W[N,K]^T ---------------
// mma.sync.m16n8k16 row.col: both A[m][k] and W[n][k] row-major in smem,
// loaded with non-trans ldmatrix. BM=BN=128, BK=32, 8 warps (4Mx2N),
// each warp computes 32x64 (2 m-tiles x 8 n-tiles).
// EPI: 0 = bias -> bf16 ; 1 = bias + exact GELU -> bf16 ; 2 = bias + res -> fp32
#define SSTR 40  // smem row stride in bf16 (80B: 8-row ldmatrix phase conflict-free)

__device__ __forceinline__ void ldm_x4(uint32_t* r, uint32_t addr) {
    asm volatile("ldmatrix.sync.aligned.m8n8.x4.shared.b16 {%0,%1,%2,%3}, [%4];"
                 : "=r"(r[0]), "=r"(r[1]), "=r"(r[2]), "=r"(r[3]) : "r"(addr));
}
__device__ __forceinline__ void mma16816(float* c, const uint32_t* a, const uint32_t* b) {
    asm volatile(
        "mma.sync.aligned.m16n8k16.row.col.f32.bf16.bf16.f32 "
        "{%0,%1,%2,%3}, {%4,%5,%6,%7}, {%8,%9}, {%0,%1,%2,%3};"
        : "+f"(c[0]), "+f"(c[1]), "+f"(c[2]), "+f"(c[3])
        : "r"(a[0]), "r"(a[1]), "r"(a[2]), "r"(a[3]), "r"(b[0]), "r"(b[1]));
}

template <int EPI, bool GATHER>
__global__ void __launch_bounds__(256, 2)
hgemm(const __nv_bfloat16* __restrict__ A, const __nv_bfloat16* __restrict__ W,
      const float* __restrict__ bias, const float* __restrict__ res,
      void* __restrict__ Cout, int M, int N, int K) {
    __shared__ __nv_bfloat16 As[128 * SSTR];
    __shared__ __nv_bfloat16 Bs[128 * SSTR];
    int t = threadIdx.x;
    int wid = t >> 5, lane = t & 31;
    int bm = blockIdx.y << 7, bn = blockIdx.x << 7;
    int wm = (wid & 3) * 32;       // warp M offset in tile
    int wn = (wid >> 2) * 64;      // warp N offset in tile

    // loader: each thread owns rows (t/4) and (t/4)+64, 8 bf16 at col (t%4)*8
    int lrow = t >> 2;
    int lco  = (t & 3) * 8;
    size_t ar0 = (size_t)(bm + lrow), ar1 = (size_t)(bm + lrow + 64);
    if (GATHER) { ar0 = proj_gather(ar0); ar1 = proj_gather(ar1); }
    const __nv_bfloat16* Ap0 = A + ar0 * (size_t)K + lco;
    const __nv_bfloat16* Ap1 = A + ar1 * (size_t)K + lco;
    const __nv_bfloat16* Wp0 = W + (size_t)(bn + lrow) * K + lco;
    const __nv_bfloat16* Wp1 = W + (size_t)(bn + lrow + 64) * K + lco;

    float acc[2][8][4];
#pragma unroll
    for (int i = 0; i < 2; i++)
#pragma unroll
        for (int j = 0; j < 8; j++)
#pragma unroll
            for (int q = 0; q < 4; q++) acc[i][j][q] = 0.0f;

    // ldmatrix source addresses (byte)
    uint32_t a_addr0 = smem_u32(&As[(wm + (lane & 15)) * SSTR + ((lane >> 4) << 3)]);
    uint32_t b_addr0 = smem_u32(&Bs[(wn + (lane & 7) + ((lane >> 4) << 3)) * SSTR +
                                    (((lane >> 3) & 1) << 3)]);

    for (int k0 = 0; k0 < K; k0 += 32) {
        uint4 a0 = *(const uint4*)(Ap0 + k0);
        uint4 a1 = *(const uint4*)(Ap1 + k0);
        uint4 b0 = *(const uint4*)(Wp0 + k0);
        uint4 b1 = *(const uint4*)(Wp1 + k0);
        __syncthreads();
        *(uint4*)&As[lrow * SSTR + lco]        = a0;
        *(uint4*)&As[(lrow + 64) * SSTR + lco] = a1;
        *(uint4*)&Bs[lrow * SSTR + lco]        = b0;
        *(uint4*)&Bs[(lrow + 64) * SSTR + lco] = b1;
        __syncthreads();
#pragma unroll
        for (int kk = 0; kk < 2; kk++) {  // two k16 halves of BK=32
            uint32_t af[2][4];
#pragma unroll
            for (int mt = 0; mt < 2; mt++)
                ldm_x4(af[mt], a_addr0 + (mt * 16 * SSTR + kk * 16) * 2);
            uint32_t bfr[4][4];
#pragma unroll
            for (int bt = 0; bt < 4; bt++)
                ldm_x4(bfr[bt], b_addr0 + (bt * 16 * SSTR + kk * 16) * 2);
#pragma unroll
            for (int mt = 0; mt < 2; mt++)
#pragma unroll
                for (int nt = 0; nt < 8; nt++)
                    mma16816(acc[mt][nt], af[mt], &bfr[nt >> 1][(nt & 1) * 2]);
        }
    }

    // epilogue from C fragments: thread holds rows lane/4 (+8), cols (lane%4)*2 (+1)
    int r0 = lane >> 2;
    int c0 = (lane & 3) * 2;
#pragma unroll
    for (int mt = 0; mt < 2; mt++) {
#pragma unroll
        for (int half = 0; half < 2; half++) {
            int row = bm + wm + mt * 16 + r0 + half * 8;
#pragma unroll
            for (int nt = 0; nt < 8; nt++) {
                int col = bn + wn + nt * 8 + c0;
                float v0 = acc[mt][nt][half * 2 + 0] + bias[col];
                float v1 = acc[mt][nt][half * 2 + 1] + bias[col + 1];
                if (EPI == 1) {
                    v0 = 0.5f * v0 * (1.0f + erff(v0 * 0.70710678118654752f));
                    v1 = 0.5f * v1 * (1.0f + erff(v1 * 0.70710678118654752f));
                }
                if (EPI == 2) {
                    const float2 rv = *(const float2*)(res + (size_t)row * N + col);
                    float2 o = make_float2(v0 + rv.x, v1 + rv.y);
                    *(float2*)((float*)Cout + (size_t)row * N + col) = o;
                } else {
                    *(__nv_bfloat162*)((__nv_bfloat16*)Cout + (size_t)row * N + col) =
                        __floats2bfloat162_rn(v0, v1);
                }
            }
        }
    }
}

// ---------------- Windowed attention: one block per (window, head) ---------
__global__ void __launch_bounds__(128)
attn_kernel(const __nv_bfloat16* __restrict__ qkv, const float* __restrict__ rpb,
            __nv_bfloat16* __restrict__ out) {
    __shared__ float qs[49 * 33];
    __shared__ float ks[49 * 33];
    __shared__ float vs[49 * 33];
    __shared__ float S[49 * 50];
    __shared__ int reg[49];

    int win = blockIdx.x >> 2;
    int head = blockIdx.x & 3;
    int t = threadIdx.x;
    int lane = t & 31, wid = t >> 5;

    int wrem = win & 63;
    int wh = wrem >> 3, ww = wrem & 7;
    if (t < 49) {
        int y = t / 7, xx = t - y * 7;
        int gh = wh * 7 + y, gw = ww * 7 + xx;
        int rh = gh < 49 ? 0 : (gh < 53 ? 1 : 2);
        int rw = gw < 49 ? 0 : (gw < 53 ? 1 : 2);
        reg[t] = rh * 3 + rw;
    }

    size_t base = (size_t)win * 49 * 384 + head * 32;
    const float SCALE = 0.17677669529663687f;  // 32^-0.5
    for (int nn = wid; nn < 49; nn += 4) {
        size_t rb = base + (size_t)nn * 384;
        qs[nn * 33 + lane] = __bfloat162float(qkv[rb + lane]) * SCALE;
        ks[nn * 33 + lane] = __bfloat162float(qkv[rb + 128 + lane]);
        vs[nn * 33 + lane] = __bfloat162float(qkv[rb + 256 + lane]);
    }
    __syncthreads();

    for (int idx = t; idx < 2401; idx += 128) {
        int n = idx / 49, m = idx - n * 49;
        const float* qr = &qs[n * 33];
        const float* kr = &ks[m * 33];
        float s = 0.0f;
#pragma unroll
        for (int d = 0; d < 32; d++) s = fmaf(qr[d], kr[d], s);
        int y1 = n / 7, x1 = n - y1 * 7;
        int y2 = m / 7, x2 = m - y2 * 7;
        int rpi = (y1 - y2 + 6) * 13 + (x1 - x2 + 6);
        s += rpb[rpi * 4 + head];
        if (reg[n] != reg[m]) s -= 100.0f;
        S[n * 50 + m] = s;
    }
    __syncthreads();

    for (int n = wid; n < 49; n += 4) {
        float* row = &S[n * 50];
        float v0 = row[lane];
        float v1 = (lane + 32 < 49) ? row[lane + 32] : -1e30f;
        float mx = warp_max(fmaxf(v0, v1));
        float e0 = __expf(v0 - mx);
        float e1 = (lane + 32 < 49) ? __expf(v1 - mx) : 0.0f;
        float inv = 1.0f / warp_sum(e0 + e1);
        row[lane] = e0 * inv;
        if (lane + 32 < 49) row[lane + 32] = e1 * inv;
    }
    __syncthreads();

    int d = lane;
    for (int n = wid; n < 49; n += 4) {
        float o = 0.0f;
        const float* prow = &S[n * 50];
#pragma unroll 7
        for (int m = 0; m < 49; m++) o = fmaf(prow[m], vs[m * 33 + d], o);
        out[((size_t)win * 49 + n) * 128 + head * 32 + d] = __float2bfloat16(o);
    }
}

// ---------------- launch ---------------------------------------------------
extern "C" void kernel_launch(void* const* d_in, const int* in_sizes, int n_in,
                              void* d_out, int out_size) {
    const float* x      = (const float*)d_in[0];
    const float* ln1_g  = (const float*)d_in[1];
    const float* ln1_b  = (const float*)d_in[2];
    const float* qkv_w  = (const float*)d_in[3];
    const float* qkv_b  = (const float*)d_in[4];
    const float* rpb    = (const float*)d_in[5];
    const float* proj_w = (const float*)d_in[6];
    const float* proj_b = (const float*)d_in[7];
    const float* ln2_g  = (const float*)d_in[8];
    const float* ln2_b  = (const float*)d_in[9];
    const float* fc1_w  = (const float*)d_in[10];
    const float* fc1_b  = (const float*)d_in[11];
    const float* fc2_w  = (const float*)d_in[12];
    const float* fc2_b  = (const float*)d_in[13];
    float* out = (float*)d_out;

    void* p;
    cudaGetSymbolAddress(&p, g_xw);   __nv_bfloat16* xw   = (__nv_bfloat16*)p;
    cudaGetSymbolAddress(&p, g_qkv);  __nv_bfloat16* qkvb = (__nv_bfloat16*)p;
    cudaGetSymbolAddress(&p, g_att);  __nv_bfloat16* att  = (__nv_bfloat16*)p;
    cudaGetSymbolAddress(&p, g_xres); float*         xres = (float*)p;
    cudaGetSymbolAddress(&p, g_mlp);  __nv_bfloat16* mlp  = (__nv_bfloat16*)p;
    cudaGetSymbolAddress(&p, g_wq);   __nv_bfloat16* wq = (__nv_bfloat16*)p;
    cudaGetSymbolAddress(&p, g_wp);   __nv_bfloat16* wp = (__nv_bfloat16*)p;
    cudaGetSymbolAddress(&p, g_w1);   __nv_bfloat16* w1 = (__nv_bfloat16*)p;
    cudaGetSymbolAddress(&p, g_w2);   __nv_bfloat16* w2 = (__nv_bfloat16*)p;

    // weight conversion (bf16)
    f2bf<<<48, 256>>>(qkv_w, wq, 384 * 128);
    f2bf<<<16, 256>>>(proj_w, wp, 128 * 128);
    f2bf<<<64, 256>>>(fc1_w, w1, 512 * 128);
    f2bf<<<64, 256>>>(fc2_w, w2, 128 * 512);

    const int LN_BLOCKS = (TTOK * 32) / 256;  // 25088

    // 1. LN1 + shift + window partition (bf16 out)
    ln_kernel<true><<<LN_BLOCKS, 256>>>(x, ln1_g, ln1_b, xw);
    // 2. QKV projection: (T,128) @ (384,128)^T  [HMMA tensor cores]
    hgemm<0, false><<<dim3(3, 1568), 256>>>(xw, wq, qkv_b, nullptr, qkvb,
                                            TTOK, 384, 128);
    // 3. Windowed attention
    attn_kernel<<<16384, 128>>>(qkvb, rpb, att);
    // 4. proj + window-reverse/unshift gather + residual (fp32 out)
    hgemm<2, true><<<dim3(1, 1568), 256>>>(att, wp, proj_b, x, xres,
                                           TTOK, 128, 128);
    // 5. LN2 (bf16 out)
    ln_kernel<false><<<LN_BLOCKS, 256>>>(xres, ln2_g, ln2_b, xw);
    // 6. fc1 + exact GELU (bf16 out)
    hgemm<1, false><<<dim3(4, 1568), 256>>>(xw, w1, fc1_b, nullptr, mlp,
                                            TTOK, 512, 128);
    // 7. fc2 + residual -> output (fp32)
    hgemm<2, false><<<dim3(1, 1568), 256>>>(mlp, w2, fc2_b, xres, out,
                                            TTOK, 128, 512);
}

// round 13
// speedup vs baseline: 3.3207x; 1.3521x over previous
#include <cuda_runtime.h>
#include <cuda_bf16.h>
#include <math.h>
#include <stdint.h>

#define TTOK 200704          // B*H*W = 64*56*56 tokens
// C=128, QKD=128, HID=512, NH=4, HD=32, WS=7, N=49, NW=64

// ---------------- scratch (device globals; no allocation allowed) ----------
__device__ __nv_bfloat16 g_xw [(size_t)TTOK * 128];   // LN output (bf16)
__device__ __nv_bfloat16 g_qkv[(size_t)TTOK * 384];   // qkv (windowed, bf16)
__device__ __nv_bfloat16 g_att[(size_t)TTOK * 128];   // attn out (windowed, bf16)
__device__ float         g_xres[(size_t)TTOK * 128];  // x + proj (natural, fp32)
__device__ __nv_bfloat16 g_mlp[(size_t)TTOK * 512];   // gelu(fc1) (bf16)
__device__ __nv_bfloat16 g_wq[384 * 128];
__device__ __nv_bfloat16 g_wp[128 * 128];
__device__ __nv_bfloat16 g_w1[512 * 128];
__device__ __nv_bfloat16 g_w2[128 * 512];

__device__ __forceinline__ uint32_t smem_u32(const void* p) {
    return (uint32_t)__cvta_generic_to_shared(p);
}
__device__ __forceinline__ float warp_sum(float v) {
#pragma unroll
    for (int o = 16; o; o >>= 1) v += __shfl_xor_sync(0xffffffffu, v, o);
    return v;
}
__device__ __forceinline__ float warp_max(float v) {
#pragma unroll
    for (int o = 16; o; o >>= 1) v = fmaxf(v, __shfl_xor_sync(0xffffffffu, v, o));
    return v;
}
__device__ __forceinline__ void cp16(uint32_t dst, const void* src) {
    asm volatile("cp.async.cg.shared.global [%0], [%1], 16;" :: "r"(dst), "l"(src));
}
__device__ __forceinline__ void cp_commit() {
    asm volatile("cp.async.commit_group;" ::: "memory");
}
template <int N>
__device__ __forceinline__ void cp_wait() {
    asm volatile("cp.async.wait_group %0;" :: "n"(N) : "memory");
}

// ---------------- fp32 -> bf16 weight conversion (all 4 in one launch) -----
__global__ void f2bf_all(const float* __restrict__ s0, __nv_bfloat16* __restrict__ d0, int n0,
                         const float* __restrict__ s1, __nv_bfloat16* __restrict__ d1, int n1,
                         const float* __restrict__ s2, __nv_bfloat16* __restrict__ d2, int n2,
                         const float* __restrict__ s3, __nv_bfloat16* __restrict__ d3, int n3) {
    int i = (blockIdx.x * blockDim.x + threadIdx.x) * 4;
    const float* s; __nv_bfloat16* d;
    if (i < n0) { s = s0 + i; d = d0 + i; }
    else if ((i -= n0) < n1) { s = s1 + i; d = d1 + i; }
    else if ((i -= n1) < n2) { s = s2 + i; d = d2 + i; }
    else if ((i -= n2) < n3) { s = s3 + i; d = d3 + i; }
    else return;
    float4 v = *(const float4*)s;
    __nv_bfloat162* dp = (__nv_bfloat162*)d;
    dp[0] = __floats2bfloat162_rn(v.x, v.y);
    dp[1] = __floats2bfloat162_rn(v.z, v.w);
}

// ---------------- LayerNorm (warp/token), bf16 out. GATHER fuses
// roll(-3,-3) + window partition into the source index. ---------------------
template <bool GATHER>
__global__ void ln_kernel(const float* __restrict__ x, const float* __restrict__ g,
                          const float* __restrict__ b, __nv_bfloat16* __restrict__ out) {
    int gt = blockIdx.x * blockDim.x + threadIdx.x;
    int tok = gt >> 5, lane = gt & 31;
    if (tok >= TTOK) return;
    size_t src;
    if (GATHER) {
        int win = tok / 49, n = tok - win * 49;
        int bb = win >> 6, wrem = win & 63;
        int ny = n / 7, nx = n - ny * 7;
        int gh = (wrem >> 3) * 7 + ny;
        int gw = (wrem & 7) * 7 + nx;
        int sh = gh + 3; if (sh >= 56) sh -= 56;
        int sw = gw + 3; if (sw >= 56) sw -= 56;
        src = (size_t)bb * 3136 + sh * 56 + sw;
    } else {
        src = (size_t)tok;
    }
    float4 v = ((const float4*)(x + src * 128))[lane];
    float mu = warp_sum(v.x + v.y + v.z + v.w) * (1.0f / 128.0f);
    float dx = v.x - mu, dy = v.y - mu, dz = v.z - mu, dw = v.w - mu;
    float var = warp_sum(dx * dx + dy * dy + dz * dz + dw * dw) * (1.0f / 128.0f);
    float inv = rsqrtf(var + 1e-5f);
    float4 gg = ((const float4*)g)[lane];
    float4 bv = ((const float4*)b)[lane];
    __nv_bfloat162* op = (__nv_bfloat162*)(out + (size_t)tok * 128);
    op[lane * 2]     = __floats2bfloat162_rn(dx * inv * gg.x + bv.x, dy * inv * gg.y + bv.y);
    op[lane * 2 + 1] = __floats2bfloat162_rn(dz * inv * gg.z + bv.z, dw * inv * gg.w + bv.w);
}

// natural-order output row -> windowed-order attention row
__device__ __forceinline__ size_t proj_gather(size_t m) {
    int bb = (int)(m / 3136);
    int r  = (int)(m - (size_t)bb * 3136);
    int h = r / 56, w = r - h * 56;
    int gh = h + 53; if (gh >= 56) gh -= 56;
    int gw = w + 53; if (gw >= 56) gw -= 56;
    int win = bb * 64 + (gh / 7) * 8 + (gw / 7);
    int n = (gh % 7) * 7 + (gw % 7);
    return (size_t)win * 49 + n;
}

// ---------------- bf16 HMMA GEMM with cp.async 2-stage pipeline ------------
// C[M,N] = A[M,K] @ W[N,K]^T. BM=BN=128, BK=32, 8 warps (4Mx2N), each warp
// 32x64. Both tiles row-major [row][k], stride 40 bf16 (conflict-free ldmatrix).
// EPI: 0 = bias -> bf16 ; 1 = bias + exact GELU -> bf16 ; 2 = bias + res -> fp32
#define SSTR 40

__device__ __forceinline__ void ldm_x4(uint32_t* r, uint32_t addr) {
    asm volatile("ldmatrix.sync.aligned.m8n8.x4.shared.b16 {%0,%1,%2,%3}, [%4];"
                 : "=r"(r[0]), "=r"(r[1]), "=r"(r[2]), "=r"(r[3]) : "r"(addr));
}
__device__ __forceinline__ void mma16816(float* c, const uint32_t* a, const uint32_t* b) {
    asm volatile(
        "mma.sync.aligned.m16n8k16.row.col.f32.bf16.bf16.f32 "
        "{%0,%1,%2,%3}, {%4,%5,%6,%7}, {%8,%9}, {%0,%1,%2,%3};"
        : "+f"(c[0]), "+f"(c[1]), "+f"(c[2]), "+f"(c[3])
        : "r"(a[0]), "r"(a[1]), "r"(a[2]), "r"(a[3]), "r"(b[0]), "r"(b[1]));
}

template <int EPI, bool GATHER>
__global__ void __launch_bounds__(256, 2)
hgemm(const __nv_bfloat16* __restrict__ A, const __nv_bfloat16* __restrict__ W,
      const float* __restrict__ bias, const float* __restrict__ res,
      void* __restrict__ Cout, int M, int N, int K) {
    __shared__ __nv_bfloat16 As[2][128 * SSTR];
    __shared__ __nv_bfloat16 Bs[2][128 * SSTR];
    int t = threadIdx.x;
    int wid = t >> 5, lane = t & 31;
    int bm = blockIdx.y << 7, bn = blockIdx.x << 7;
    int wm = (wid & 3) * 32;       // warp M offset
    int wn = (wid >> 2) * 64;      // warp N offset

    // loader: one row per 2 threads; thread covers 2x16B chunks of the 64B row
    int lrow = t >> 1;
    int half = t & 1;              // k-half: elems half*16 + {0,8}
    size_t ar = (size_t)(bm + lrow);
    if (GATHER) ar = proj_gather(ar);
    const __nv_bfloat16* Ap = A + ar * (size_t)K + half * 16;
    const __nv_bfloat16* Wp = W + (size_t)(bn + lrow) * K + half * 16;
    uint32_t sA = smem_u32(&As[0][0]) + lrow * (SSTR * 2) + half * 32;
    uint32_t sB = smem_u32(&Bs[0][0]) + lrow * (SSTR * 2) + half * 32;
    const uint32_t STG = 128 * SSTR * 2;  // bytes per stage

    int nk = K >> 5;
    // prologue: prefetch chunks 0 and 1
    {
        cp16(sA, Ap); cp16(sA + 16, Ap + 8);
        cp16(sB, Wp); cp16(sB + 16, Wp + 8);
        cp_commit();
        cp16(sA + STG, Ap + 32); cp16(sA + STG + 16, Ap + 40);
        cp16(sB + STG, Wp + 32); cp16(sB + STG + 16, Wp + 40);
        cp_commit();
    }

    float acc[2][8][4];
#pragma unroll
    for (int i = 0; i < 2; i++)
#pragma unroll
        for (int j = 0; j < 8; j++)
#pragma unroll
            for (int q = 0; q < 4; q++) acc[i][j][q] = 0.0f;

    uint32_t a_addr0 = smem_u32(&As[0][(wm + (lane & 15)) * SSTR + ((lane >> 4) << 3)]);
    uint32_t b_addr0 = smem_u32(&Bs[0][(wn + (lane & 7) + ((lane >> 4) << 3)) * SSTR +
                                       (((lane >> 3) & 1) << 3)]);

    for (int c = 0; c < nk; c++) {
        if (c + 1 < nk) cp_wait<1>(); else cp_wait<0>();
        __syncthreads();
        uint32_t soff = (c & 1) * STG;
#pragma unroll
        for (int kk = 0; kk < 2; kk++) {
            uint32_t af[2][4];
#pragma unroll
            for (int mt = 0; mt < 2; mt++)
                ldm_x4(af[mt], a_addr0 + soff + (mt * 16 * SSTR + kk * 16) * 2);
            uint32_t bfr[4][4];
#pragma unroll
            for (int bt = 0; bt < 4; bt++)
                ldm_x4(bfr[bt], b_addr0 + soff + (bt * 16 * SSTR + kk * 16) * 2);
#pragma unroll
            for (int mt = 0; mt < 2; mt++)
#pragma unroll
                for (int nt = 0; nt < 8; nt++)
                    mma16816(acc[mt][nt], af[mt], &bfr[nt >> 1][(nt & 1) * 2]);
        }
        if (c + 2 < nk) {
            __syncthreads();  // buffer (c&1) fully consumed by all warps
            const __nv_bfloat16* ap = Ap + (c + 2) * 32;
            const __nv_bfloat16* wp = Wp + (c + 2) * 32;
            cp16(sA + soff, ap); cp16(sA + soff + 16, ap + 8);
            cp16(sB + soff, wp); cp16(sB + soff + 16, wp + 8);
            cp_commit();
        }
    }

    // epilogue from C fragments: thread holds rows lane/4 (+8), cols (lane%4)*2 (+1)
    int r0 = lane >> 2;
    int c0 = (lane & 3) * 2;
#pragma unroll
    for (int mt = 0; mt < 2; mt++) {
#pragma unroll
        for (int hf = 0; hf < 2; hf++) {
            int row = bm + wm + mt * 16 + r0 + hf * 8;
#pragma unroll
            for (int nt = 0; nt < 8; nt++) {
                int col = bn + wn + nt * 8 + c0;
                float v0 = acc[mt][nt][hf * 2 + 0] + bias[col];
                float v1 = acc[mt][nt][hf * 2 + 1] + bias[col + 1];
                if (EPI == 1) {
                    v0 = 0.5f * v0 * (1.0f + erff(v0 * 0.70710678118654752f));
                    v1 = 0.5f * v1 * (1.0f + erff(v1 * 0.70710678118654752f));
                }
                if (EPI == 2) {
                    const float2 rv = *(const float2*)(res + (size_t)row * N + col);
                    float2 o = make_float2(v0 + rv.x, v1 + rv.y);
                    *(float2*)((float*)Cout + (size_t)row * N + col) = o;
                } else {
                    *(__nv_bfloat162*)((__nv_bfloat16*)Cout + (size_t)row * N + col) =
                        __floats2bfloat162_rn(v0, v1);
                }
            }
        }
    }
}

// ---------------- Windowed attention v2: register-tiled --------------------
// One block per (window, head), 128 threads. QK^T: 16x8 thread grid, each
// thread a 4x7 tile of S via float4 smem loads. V stored transposed so PV
// reads float4 along m with 4-row P reuse.
#define QSTR 36   // q/k row stride (floats, 16B-aligned rows)
#define VSTR 60   // vT row stride
#define SSTRD 60  // S row stride

__global__ void __launch_bounds__(128)
attn_kernel(const __nv_bfloat16* __restrict__ qkv, const float* __restrict__ rpb,
            __nv_bfloat16* __restrict__ out) {
    __shared__ float qs[64 * QSTR];
    __shared__ float ks[56 * QSTR];
    __shared__ float vsT[32 * VSTR];
    __shared__ float S[64 * SSTRD];
    __shared__ float rps[169];
    __shared__ int reg[49];

    int win = blockIdx.x >> 2;
    int head = blockIdx.x & 3;
    int t = threadIdx.x;
    int lane = t & 31, wid = t >> 5;

    int wrem = win & 63;
    int wh = wrem >> 3, ww = wrem & 7;
    if (t < 49) {
        int y = t / 7, xx = t - y * 7;
        int gh = wh * 7 + y, gw = ww * 7 + xx;
        int rh = gh < 49 ? 0 : (gh < 53 ? 1 : 2);
        int rw = gw < 49 ? 0 : (gw < 53 ? 1 : 2);
        reg[t] = rh * 3 + rw;
    }
    for (int i = t; i < 169; i += 128) rps[i] = rpb[i * 4 + head];

    size_t base = (size_t)win * 49 * 384 + head * 32;
    const float SCALE = 0.17677669529663687f;  // 32^-0.5
    for (int nn = wid; nn < 49; nn += 4) {
        size_t rb = base + (size_t)nn * 384;
        qs[nn * QSTR + lane] = __bfloat162float(qkv[rb + lane]) * SCALE;
        ks[nn * QSTR + lane] = __bfloat162float(qkv[rb + 128 + lane]);
        vsT[lane * VSTR + nn] = __bfloat162float(qkv[rb + 256 + lane]);
    }
    __syncthreads();

    // ---- S = Q@K^T + bias + mask : 4x7 tile per thread --------------------
    {
        int tr = t >> 3;          // 0..15 -> rows tr*4..tr*4+3
        int tc = t & 7;           // 0..7  -> cols tc*7..tc*7+6
        float acc[4][7];
#pragma unroll
        for (int i = 0; i < 4; i++)
#pragma unroll
            for (int j = 0; j < 7; j++) acc[i][j] = 0.0f;
        const float* qb = qs + tr * 4 * QSTR;
        const float* kb = ks + tc * 7 * QSTR;
#pragma unroll
        for (int d0 = 0; d0 < 32; d0 += 4) {
            float4 qv[4], kv[7];
#pragma unroll
            for (int i = 0; i < 4; i++) qv[i] = *(const float4*)(qb + i * QSTR + d0);
#pragma unroll
            for (int j = 0; j < 7; j++) kv[j] = *(const float4*)(kb + j * QSTR + d0);
#pragma unroll
            for (int i = 0; i < 4; i++)
#pragma unroll
                for (int j = 0; j < 7; j++)
                    acc[i][j] = fmaf(qv[i].x, kv[j].x, fmaf(qv[i].y, kv[j].y,
                               fmaf(qv[i].z, kv[j].z, fmaf(qv[i].w, kv[j].w, acc[i][j]))));
        }
#pragma unroll
        for (int i = 0; i < 4; i++) {
            int n = tr * 4 + i;
            if (n < 49) {
                int y1 = n / 7, x1 = n - y1 * 7, rn = reg[n];
#pragma unroll
                for (int j = 0; j < 7; j++) {
                    int m = tc * 7 + j;
                    if (m < 49) {
                        int y2 = m / 7, x2 = m - y2 * 7;
                        float s = acc[i][j] + rps[(y1 - y2 + 6) * 13 + (x1 - x2 + 6)];
                        if (rn != reg[m]) s -= 100.0f;
                        S[n * SSTRD + m] = s;
                    }
                }
            }
        }
    }
    __syncthreads();

    // ---- softmax over rows ------------------------------------------------
    for (int n = wid; n < 49; n += 4) {
        float* row = &S[n * SSTRD];
        float v0 = row[lane];
        float v1 = (lane + 32 < 49) ? row[lane + 32] : -1e30f;
        float mx = warp_max(fmaxf(v0, v1));
        float e0 = __expf(v0 - mx);
        float e1 = (lane + 32 < 49) ? __expf(v1 - mx) : 0.0f;
        float inv = 1.0f / warp_sum(e0 + e1);
        row[lane] = e0 * inv;
        if (lane + 32 < 49) row[lane + 32] = e1 * inv;
    }
    __syncthreads();

    // ---- out = P@V : 4 rows per warp per sweep, float4 along m ------------
    const float* vrow = vsT + lane * VSTR;   // lane = head dim d
#pragma unroll
    for (int sw = 0; sw < 4; sw++) {
        int n0 = sw * 16 + wid * 4;
        float o[4] = {0.0f, 0.0f, 0.0f, 0.0f};
#pragma unroll
        for (int m0 = 0; m0 < 48; m0 += 4) {
            float4 vv = *(const float4*)(vrow + m0);
#pragma unroll
            for (int i = 0; i < 4; i++) {
                float4 pv = *(const float4*)(S + (n0 + i) * SSTRD + m0);
                o[i] = fmaf(pv.x, vv.x, fmaf(pv.y, vv.y,
                       fmaf(pv.z, vv.z, fmaf(pv.w, vv.w, o[i]))));
            }
        }
        float vl = vrow[48];
#pragma unroll
        for (int i = 0; i < 4; i++) {
            int n = n0 + i;
            if (n < 49) {
                o[i] = fmaf(S[n * SSTRD + 48], vl, o[i]);
                out[((size_t)win * 49 + n) * 128 + head * 32 + lane] = __float2bfloat16(o[i]);
            }
        }
    }
}

// ---------------- launch ---------------------------------------------------
extern "C" void kernel_launch(void* const* d_in, const int* in_sizes, int n_in,
                              void* d_out, int out_size) {
    const float* x      = (const float*)d_in[0];
    const float* ln1_g  = (const float*)d_in[1];
    const float* ln1_b  = (const float*)d_in[2];
    const float* qkv_w  = (const float*)d_in[3];
    const float* qkv_b  = (const float*)d_in[4];
    const float* rpb    = (const float*)d_in[5];
    const float* proj_w = (const float*)d_in[6];
    const float* proj_b = (const float*)d_in[7];
    const float* ln2_g  = (const float*)d_in[8];
    const float* ln2_b  = (const float*)d_in[9];
    const float* fc1_w  = (const float*)d_in[10];
    const float* fc1_b  = (const float*)d_in[11];
    const float* fc2_w  = (const float*)d_in[12];
    const float* fc2_b  = (const float*)d_in[13];
    float* out = (float*)d_out;

    void* p;
    cudaGetSymbolAddress(&p, g_xw);   __nv_bfloat16* xw   = (__nv_bfloat16*)p;
    cudaGetSymbolAddress(&p, g_qkv);  __nv_bfloat16* qkvb = (__nv_bfloat16*)p;
    cudaGetSymbolAddress(&p, g_att);  __nv_bfloat16* att  = (__nv_bfloat16*)p;
    cudaGetSymbolAddress(&p, g_xres); float*         xres = (float*)p;
    cudaGetSymbolAddress(&p, g_mlp);  __nv_bfloat16* mlp  = (__nv_bfloat16*)p;
    cudaGetSymbolAddress(&p, g_wq);   __nv_bfloat16* wq = (__nv_bfloat16*)p;
    cudaGetSymbolAddress(&p, g_wp);   __nv_bfloat16* wp = (__nv_bfloat16*)p;
    cudaGetSymbolAddress(&p, g_w1);   __nv_bfloat16* w1 = (__nv_bfloat16*)p;
    cudaGetSymbolAddress(&p, g_w2);   __nv_bfloat16* w2 = (__nv_bfloat16*)p;

    // weight conversion (bf16), single launch
    f2bf_all<<<192, 256>>>(qkv_w, wq, 384 * 128, proj_w, wp, 128 * 128,
                           fc1_w, w1, 512 * 128, fc2_w, w2, 128 * 512);

    const int LN_BLOCKS = (TTOK * 32) / 256;  // 25088

    // 1. LN1 + shift + window partition (bf16 out)
    ln_kernel<true><<<LN_BLOCKS, 256>>>(x, ln1_g, ln1_b, xw);
    // 2. QKV projection: (T,128) @ (384,128)^T  [HMMA, cp.async pipelined]
    hgemm<0, false><<<dim3(3, 1568), 256>>>(xw, wq, qkv_b, nullptr, qkvb,
                                            TTOK, 384, 128);
    // 3. Windowed attention (register-tiled)
    attn_kernel<<<16384, 128>>>(qkvb, rpb, att);
    // 4. proj + window-reverse/unshift gather + residual (fp32 out)
    hgemm<2, true><<<dim3(1, 1568), 256>>>(att, wp, proj_b, x, xres,
                                           TTOK, 128, 128);
    // 5. LN2 (bf16 out)
    ln_kernel<false><<<LN_BLOCKS, 256>>>(xres, ln2_g, ln2_b, xw);
    // 6. fc1 + exact GELU (bf16 out)
    hgemm<1, false><<<dim3(4, 1568), 256>>>(xw, w1, fc1_b, nullptr, mlp,
                                            TTOK, 512, 128);
    // 7. fc2 + residual -> output (fp32)
    hgemm<2, false><<<dim3(1, 1568), 256>>>(mlp, w2, fc2_b, xres, out,
                                            TTOK, 128, 512);
}

// round 14
// speedup vs baseline: 4.3027x; 1.2957x over previous
#include <cuda_runtime.h>
#include <cuda_bf16.h>
#include <math.h>
#include <stdint.h>

#define TTOK 200704          // B*H*W = 64*56*56 tokens
// C=128, QKD=128, HID=512, NH=4, HD=32, WS=7, N=49, NW=64

// ---------------- scratch (device globals; no allocation allowed) ----------
__device__ __nv_bfloat16 g_xw [(size_t)TTOK * 128];   // LN output (bf16)
__device__ __nv_bfloat16 g_qkv[(size_t)TTOK * 384];   // qkv (windowed, bf16)
__device__ __nv_bfloat16 g_att[(size_t)TTOK * 128];   // attn out (windowed, bf16)
__device__ float         g_xres[(size_t)TTOK * 128];  // x + proj (natural, fp32)
__device__ __nv_bfloat16 g_mlp[(size_t)TTOK * 512];   // gelu(fc1) (bf16)
__device__ __nv_bfloat16 g_wq[384 * 128];
__device__ __nv_bfloat16 g_wp[128 * 128];
__device__ __nv_bfloat16 g_w1[512 * 128];
__device__ __nv_bfloat16 g_w2[128 * 512];

__device__ __forceinline__ uint32_t smem_u32(const void* p) {
    return (uint32_t)__cvta_generic_to_shared(p);
}
__device__ __forceinline__ float warp_sum(float v) {
#pragma unroll
    for (int o = 16; o; o >>= 1) v += __shfl_xor_sync(0xffffffffu, v, o);
    return v;
}
__device__ __forceinline__ void cp16(uint32_t dst, const void* src) {
    asm volatile("cp.async.cg.shared.global [%0], [%1], 16;" :: "r"(dst), "l"(src));
}
__device__ __forceinline__ void cp_commit() {
    asm volatile("cp.async.commit_group;" ::: "memory");
}
template <int N>
__device__ __forceinline__ void cp_wait() {
    asm volatile("cp.async.wait_group %0;" :: "n"(N) : "memory");
}
__device__ __forceinline__ void ldm_x4(uint32_t* r, uint32_t addr) {
    asm volatile("ldmatrix.sync.aligned.m8n8.x4.shared.b16 {%0,%1,%2,%3}, [%4];"
                 : "=r"(r[0]), "=r"(r[1]), "=r"(r[2]), "=r"(r[3]) : "r"(addr));
}
__device__ __forceinline__ void ldm_x4_t(uint32_t* r, uint32_t addr) {
    asm volatile("ldmatrix.sync.aligned.m8n8.x4.trans.shared.b16 {%0,%1,%2,%3}, [%4];"
                 : "=r"(r[0]), "=r"(r[1]), "=r"(r[2]), "=r"(r[3]) : "r"(addr));
}
__device__ __forceinline__ void mma16816(float* c, const uint32_t* a, const uint32_t* b) {
    asm volatile(
        "mma.sync.aligned.m16n8k16.row.col.f32.bf16.bf16.f32 "
        "{%0,%1,%2,%3}, {%4,%5,%6,%7}, {%8,%9}, {%0,%1,%2,%3};"
        : "+f"(c[0]), "+f"(c[1]), "+f"(c[2]), "+f"(c[3])
        : "r"(a[0]), "r"(a[1]), "r"(a[2]), "r"(a[3]), "r"(b[0]), "r"(b[1]));
}
__device__ __forceinline__ uint32_t packbf2(float a, float b) {
    __nv_bfloat162 h = __floats2bfloat162_rn(a, b);
    return *(uint32_t*)&h;
}

// ---------------- fp32 -> bf16 weight conversion (all 4 in one launch) -----
__global__ void f2bf_all(const float* __restrict__ s0, __nv_bfloat16* __restrict__ d0, int n0,
                         const float* __restrict__ s1, __nv_bfloat16* __restrict__ d1, int n1,
                         const float* __restrict__ s2, __nv_bfloat16* __restrict__ d2, int n2,
                         const float* __restrict__ s3, __nv_bfloat16* __restrict__ d3, int n3) {
    int i = (blockIdx.x * blockDim.x + threadIdx.x) * 4;
    const float* s; __nv_bfloat16* d;
    if (i < n0) { s = s0 + i; d = d0 + i; }
    else if ((i -= n0) < n1) { s = s1 + i; d = d1 + i; }
    else if ((i -= n1) < n2) { s = s2 + i; d = d2 + i; }
    else if ((i -= n2) < n3) { s = s3 + i; d = d3 + i; }
    else return;
    float4 v = *(const float4*)s;
    __nv_bfloat162* dp = (__nv_bfloat162*)d;
    dp[0] = __floats2bfloat162_rn(v.x, v.y);
    dp[1] = __floats2bfloat162_rn(v.z, v.w);
}

// ---------------- LayerNorm (warp/token), bf16 out. GATHER fuses
// roll(-3,-3) + window partition into the source index. ---------------------
template <bool GATHER>
__global__ void ln_kernel(const float* __restrict__ x, const float* __restrict__ g,
                          const float* __restrict__ b, __nv_bfloat16* __restrict__ out) {
    int gt = blockIdx.x * blockDim.x + threadIdx.x;
    int tok = gt >> 5, lane = gt & 31;
    if (tok >= TTOK) return;
    size_t src;
    if (GATHER) {
        int win = tok / 49, n = tok - win * 49;
        int bb = win >> 6, wrem = win & 63;
        int ny = n / 7, nx = n - ny * 7;
        int gh = (wrem >> 3) * 7 + ny;
        int gw = (wrem & 7) * 7 + nx;
        int sh = gh + 3; if (sh >= 56) sh -= 56;
        int sw = gw + 3; if (sw >= 56) sw -= 56;
        src = (size_t)bb * 3136 + sh * 56 + sw;
    } else {
        src = (size_t)tok;
    }
    float4 v = ((const float4*)(x + src * 128))[lane];
    float mu = warp_sum(v.x + v.y + v.z + v.w) * (1.0f / 128.0f);
    float dx = v.x - mu, dy = v.y - mu, dz = v.z - mu, dw = v.w - mu;
    float var = warp_sum(dx * dx + dy * dy + dz * dz + dw * dw) * (1.0f / 128.0f);
    float inv = rsqrtf(var + 1e-5f);
    float4 gg = ((const float4*)g)[lane];
    float4 bv = ((const float4*)b)[lane];
    __nv_bfloat162* op = (__nv_bfloat162*)(out + (size_t)tok * 128);
    op[lane * 2]     = __floats2bfloat162_rn(dx * inv * gg.x + bv.x, dy * inv * gg.y + bv.y);
    op[lane * 2 + 1] = __floats2bfloat162_rn(dz * inv * gg.z + bv.z, dw * inv * gg.w + bv.w);
}

// natural-order output row -> windowed-order attention row
__device__ __forceinline__ size_t proj_gather(size_t m) {
    int bb = (int)(m / 3136);
    int r  = (int)(m - (size_t)bb * 3136);
    int h = r / 56, w = r - h * 56;
    int gh = h + 53; if (gh >= 56) gh -= 56;
    int gw = w + 53; if (gw >= 56) gw -= 56;
    int win = bb * 64 + (gh / 7) * 8 + (gw / 7);
    int n = (gh % 7) * 7 + (gw % 7);
    return (size_t)win * 49 + n;
}

// ---------------- bf16 HMMA GEMM with cp.async 2-stage pipeline ------------
#define SSTR 40

template <int EPI, bool GATHER>
__global__ void __launch_bounds__(256, 2)
hgemm(const __nv_bfloat16* __restrict__ A, const __nv_bfloat16* __restrict__ W,
      const float* __restrict__ bias, const float* __restrict__ res,
      void* __restrict__ Cout, int M, int N, int K) {
    __shared__ __nv_bfloat16 As[2][128 * SSTR];
    __shared__ __nv_bfloat16 Bs[2][128 * SSTR];
    int t = threadIdx.x;
    int wid = t >> 5, lane = t & 31;
    int bm = blockIdx.y << 7, bn = blockIdx.x << 7;
    int wm = (wid & 3) * 32;
    int wn = (wid >> 2) * 64;

    int lrow = t >> 1;
    int half = t & 1;
    size_t ar = (size_t)(bm + lrow);
    if (GATHER) ar = proj_gather(ar);
    const __nv_bfloat16* Ap = A + ar * (size_t)K + half * 16;
    const __nv_bfloat16* Wp = W + (size_t)(bn + lrow) * K + half * 16;
    uint32_t sA = smem_u32(&As[0][0]) + lrow * (SSTR * 2) + half * 32;
    uint32_t sB = smem_u32(&Bs[0][0]) + lrow * (SSTR * 2) + half * 32;
    const uint32_t STG = 128 * SSTR * 2;

    int nk = K >> 5;
    {
        cp16(sA, Ap); cp16(sA + 16, Ap + 8);
        cp16(sB, Wp); cp16(sB + 16, Wp + 8);
        cp_commit();
        cp16(sA + STG, Ap + 32); cp16(sA + STG + 16, Ap + 40);
        cp16(sB + STG, Wp + 32); cp16(sB + STG + 16, Wp + 40);
        cp_commit();
    }

    float acc[2][8][4];
#pragma unroll
    for (int i = 0; i < 2; i++)
#pragma unroll
        for (int j = 0; j < 8; j++)
#pragma unroll
            for (int q = 0; q < 4; q++) acc[i][j][q] = 0.0f;

    uint32_t a_addr0 = smem_u32(&As[0][(wm + (lane & 15)) * SSTR + ((lane >> 4) << 3)]);
    uint32_t b_addr0 = smem_u32(&Bs[0][(wn + (lane & 7) + ((lane >> 4) << 3)) * SSTR +
                                       (((lane >> 3) & 1) << 3)]);

    for (int c = 0; c < nk; c++) {
        if (c + 1 < nk) cp_wait<1>(); else cp_wait<0>();
        __syncthreads();
        uint32_t soff = (c & 1) * STG;
#pragma unroll
        for (int kk = 0; kk < 2; kk++) {
            uint32_t af[2][4];
#pragma unroll
            for (int mt = 0; mt < 2; mt++)
                ldm_x4(af[mt], a_addr0 + soff + (mt * 16 * SSTR + kk * 16) * 2);
            uint32_t bfr[4][4];
#pragma unroll
            for (int bt = 0; bt < 4; bt++)
                ldm_x4(bfr[bt], b_addr0 + soff + (bt * 16 * SSTR + kk * 16) * 2);
#pragma unroll
            for (int mt = 0; mt < 2; mt++)
#pragma unroll
                for (int nt = 0; nt < 8; nt++)
                    mma16816(acc[mt][nt], af[mt], &bfr[nt >> 1][(nt & 1) * 2]);
        }
        if (c + 2 < nk) {
            __syncthreads();
            const __nv_bfloat16* ap = Ap + (c + 2) * 32;
            const __nv_bfloat16* wp = Wp + (c + 2) * 32;
            cp16(sA + soff, ap); cp16(sA + soff + 16, ap + 8);
            cp16(sB + soff, wp); cp16(sB + soff + 16, wp + 8);
            cp_commit();
        }
    }

    int r0 = lane >> 2;
    int c0 = (lane & 3) * 2;
#pragma unroll
    for (int mt = 0; mt < 2; mt++) {
#pragma unroll
        for (int hf = 0; hf < 2; hf++) {
            int row = bm + wm + mt * 16 + r0 + hf * 8;
#pragma unroll
            for (int nt = 0; nt < 8; nt++) {
                int col = bn + wn + nt * 8 + c0;
                float v0 = acc[mt][nt][hf * 2 + 0] + bias[col];
                float v1 = acc[mt][nt][hf * 2 + 1] + bias[col + 1];
                if (EPI == 1) {
                    v0 = 0.5f * v0 * (1.0f + erff(v0 * 0.70710678118654752f));
                    v1 = 0.5f * v1 * (1.0f + erff(v1 * 0.70710678118654752f));
                }
                if (EPI == 2) {
                    const float2 rv = *(const float2*)(res + (size_t)row * N + col);
                    float2 o = make_float2(v0 + rv.x, v1 + rv.y);
                    *(float2*)((float*)Cout + (size_t)row * N + col) = o;
                } else {
                    *(__nv_bfloat162*)((__nv_bfloat16*)Cout + (size_t)row * N + col) =
                        __floats2bfloat162_rn(v0, v1);
                }
            }
        }
    }
}

// ---------------- Windowed attention v3: HMMA, one block per window --------
// 256 threads = 8 warps; 2 warps per head (warp handles 32 S-rows).
// QK^T and PV on tensor cores; softmax entirely in registers.
#define ASTR 136   // smem row stride in bf16 halves (272B, conflict-free ldmatrix)
#define ATTN_SMEM (192 * ASTR * 2 + 676 * 4 + 64 * 4)

__global__ void __launch_bounds__(256)
attn_kernel(const __nv_bfloat16* __restrict__ qkv, const float* __restrict__ rpb,
            __nv_bfloat16* __restrict__ out) {
    extern __shared__ __nv_bfloat16 sm[];
    __nv_bfloat16* qs  = sm;                 // [64][ASTR]
    __nv_bfloat16* ksm = sm + 64 * ASTR;     // [64][ASTR]
    __nv_bfloat16* vsm = sm + 128 * ASTR;    // [64][ASTR]
    float* rps4 = (float*)(sm + 192 * ASTR); // [4][169]
    int* regid  = (int*)(rps4 + 676);        // [49]

    int win = blockIdx.x;
    int t = threadIdx.x;
    int lane = t & 31, wid = t >> 5;
    int head = wid >> 1;
    int ms = (wid & 1) * 32;                  // warp's S-row base

    int wrem = win & 63;
    int wh = wrem >> 3, ww = wrem & 7;
    if (t < 49) {
        int y = (t * 2341) >> 14, xx = t - y * 7;
        int gh = wh * 7 + y, gw = ww * 7 + xx;
        int rh = gh < 49 ? 0 : (gh < 53 ? 1 : 2);
        int rw = gw < 49 ? 0 : (gw < 53 ? 1 : 2);
        regid[t] = rh * 3 + rw;
    }
    for (int i = t; i < 676; i += 256) {
        int h = i / 169, r = i - h * 169;
        rps4[h * 169 + r] = rpb[r * 4 + h];
    }
    // load qkv (49 tokens x 384 halves = 2352 16B-chunks); zero pad rows 49..63
    size_t base = (size_t)win * 49 * 384;
    for (int idx = t; idx < 2352; idx += 256) {
        int nn = idx / 48, c = idx - nn * 48;
        uint4 v = *(const uint4*)(qkv + base + nn * 384 + c * 8);
        int sec = c >> 4, col = (c & 15) * 8;
        __nv_bfloat16* dst = (sec == 0) ? qs : (sec == 1) ? ksm : vsm;
        *(uint4*)&dst[nn * ASTR + col] = v;
    }
    uint4 z = make_uint4(0, 0, 0, 0);
    for (int idx = t; idx < 720; idx += 256) {  // 15 pad rows x 48 chunks
        int pr = idx / 48, c = idx - pr * 48;
        int rr = 49 + pr;
        int sec = c >> 4, col = (c & 15) * 8;
        __nv_bfloat16* dst = (sec == 0) ? qs : (sec == 1) ? ksm : vsm;
        *(uint4*)&dst[rr * ASTR + col] = z;
    }
    __syncthreads();

    // ---- S = Q@K^T on HMMA: sc[2 m-tiles][7 n8-tiles][4] --------------------
    float sc[2][7][4];
#pragma unroll
    for (int i = 0; i < 2; i++)
#pragma unroll
        for (int j = 0; j < 7; j++)
#pragma unroll
            for (int q = 0; q < 4; q++) sc[i][j][q] = 0.0f;

    uint32_t a_base = smem_u32(&qs[(ms + (lane & 15)) * ASTR + head * 32 + ((lane >> 4) << 3)]);
    uint32_t b_base = smem_u32(&ksm[((lane & 7) + ((lane >> 4) << 3)) * ASTR + head * 32 +
                                    (((lane >> 3) & 1) << 3)]);
#pragma unroll
    for (int kk = 0; kk < 2; kk++) {
        uint32_t af[2][4];
#pragma unroll
        for (int mt = 0; mt < 2; mt++)
            ldm_x4(af[mt], a_base + (mt * 16 * ASTR + kk * 16) * 2);
        uint32_t bfr[4][4];
#pragma unroll
        for (int bt = 0; bt < 4; bt++)
            ldm_x4(bfr[bt], b_base + (bt * 16 * ASTR + kk * 16) * 2);
#pragma unroll
        for (int mt = 0; mt < 2; mt++)
#pragma unroll
            for (int nt = 0; nt < 7; nt++)
                mma16816(sc[mt][nt], af[mt], &bfr[nt >> 1][(nt & 1) * 2]);
    }

    // ---- scale + rel-pos bias + shift mask, in-register --------------------
    const float SCALE = 0.17677669529663687f;  // 32^-0.5
    int rY[2][2], rX[2][2], rR[2][2]; bool rV[2][2];
#pragma unroll
    for (int mt = 0; mt < 2; mt++)
#pragma unroll
        for (int rh = 0; rh < 2; rh++) {
            int r = ms + mt * 16 + (lane >> 2) + rh * 8;
            bool v = r < 49;
            rV[mt][rh] = v;
            int rc = v ? r : 0;
            rY[mt][rh] = (rc * 2341) >> 14;
            rX[mt][rh] = rc - rY[mt][rh] * 7;
            rR[mt][rh] = regid[rc];
        }
#pragma unroll
    for (int nt = 0; nt < 7; nt++) {
#pragma unroll
        for (int e = 0; e < 2; e++) {
            int m = nt * 8 + (lane & 3) * 2 + e;
            bool mv = m < 49;
            int mc = mv ? m : 0;
            int y2 = (mc * 2341) >> 14, x2 = mc - y2 * 7;
            int rm = regid[mc];
#pragma unroll
            for (int mt = 0; mt < 2; mt++)
#pragma unroll
                for (int rh = 0; rh < 2; rh++) {
                    float s = sc[mt][nt][rh * 2 + e] * SCALE;
                    if (mv && rV[mt][rh]) {
                        s += rps4[head * 169 + (rY[mt][rh] - y2 + 6) * 13 +
                                  (rX[mt][rh] - x2 + 6)];
                        if (rR[mt][rh] != rm) s -= 100.0f;
                    } else {
                        s = -1e30f;
                    }
                    sc[mt][nt][rh * 2 + e] = s;
                }
        }
    }

    // ---- register softmax: row spread over 4 lanes (shfl_xor 1,2) ----------
    float rinv[2][2];
#pragma unroll
    for (int mt = 0; mt < 2; mt++)
#pragma unroll
        for (int rh = 0; rh < 2; rh++) {
            float mx = -1e30f;
#pragma unroll
            for (int nt = 0; nt < 7; nt++)
                mx = fmaxf(mx, fmaxf(sc[mt][nt][rh * 2], sc[mt][nt][rh * 2 + 1]));
            mx = fmaxf(mx, __shfl_xor_sync(0xffffffffu, mx, 1));
            mx = fmaxf(mx, __shfl_xor_sync(0xffffffffu, mx, 2));
            float sum = 0.0f;
#pragma unroll
            for (int nt = 0; nt < 7; nt++) {
                float e0 = __expf(sc[mt][nt][rh * 2] - mx);
                float e1 = __expf(sc[mt][nt][rh * 2 + 1] - mx);
                sc[mt][nt][rh * 2] = e0;
                sc[mt][nt][rh * 2 + 1] = e1;
                sum += e0 + e1;
            }
            sum += __shfl_xor_sync(0xffffffffu, sum, 1);
            sum += __shfl_xor_sync(0xffffffffu, sum, 2);
            rinv[mt][rh] = rV[mt][rh] ? (1.0f / sum) : 0.0f;
        }

    // ---- out = P@V on HMMA: P fragments packed from sc ----------------------
    float oc[2][4][4];
#pragma unroll
    for (int i = 0; i < 2; i++)
#pragma unroll
        for (int j = 0; j < 4; j++)
#pragma unroll
            for (int q = 0; q < 4; q++) oc[i][j][q] = 0.0f;

    uint32_t vb = smem_u32(&vsm[(lane & 15) * ASTR + head * 32 + ((lane >> 4) << 3)]);
#pragma unroll
    for (int ks = 0; ks < 4; ks++) {
        uint32_t bv[2][4];
        ldm_x4_t(bv[0], vb + (ks * 16 * ASTR) * 2);
        ldm_x4_t(bv[1], vb + (ks * 16 * ASTR + 16) * 2);
#pragma unroll
        for (int mt = 0; mt < 2; mt++) {
            float il = rinv[mt][0], ih = rinv[mt][1];
            int n0 = 2 * ks, n1 = 2 * ks + 1;
            uint32_t a[4];
            a[0] = packbf2(sc[mt][n0][0] * il, sc[mt][n0][1] * il);
            a[1] = packbf2(sc[mt][n0][2] * ih, sc[mt][n0][3] * ih);
            if (n1 < 7) {
                a[2] = packbf2(sc[mt][n1][0] * il, sc[mt][n1][1] * il);
                a[3] = packbf2(sc[mt][n1][2] * ih, sc[mt][n1][3] * ih);
            } else {
                a[2] = 0u; a[3] = 0u;
            }
#pragma unroll
            for (int dt = 0; dt < 4; dt++)
                mma16816(oc[mt][dt], a, &bv[dt >> 1][(dt & 1) * 2]);
        }
    }

    // ---- store from PV fragments -------------------------------------------
    size_t ob = (size_t)win * 49 * 128 + head * 32;
#pragma unroll
    for (int mt = 0; mt < 2; mt++)
#pragma unroll
        for (int rh = 0; rh < 2; rh++) {
            int r = ms + mt * 16 + (lane >> 2) + rh * 8;
            if (r < 49) {
#pragma unroll
                for (int dt = 0; dt < 4; dt++) {
                    int d = dt * 8 + (lane & 3) * 2;
                    __nv_bfloat162 o2 = __floats2bfloat162_rn(oc[mt][dt][rh * 2],
                                                              oc[mt][dt][rh * 2 + 1]);
                    *(__nv_bfloat162*)(out + ob + (size_t)r * 128 + d) = o2;
                }
            }
        }
}

// ---------------- launch ---------------------------------------------------
extern "C" void kernel_launch(void* const* d_in, const int* in_sizes, int n_in,
                              void* d_out, int out_size) {
    const float* x      = (const float*)d_in[0];
    const float* ln1_g  = (const float*)d_in[1];
    const float* ln1_b  = (const float*)d_in[2];
    const float* qkv_w  = (const float*)d_in[3];
    const float* qkv_b  = (const float*)d_in[4];
    const float* rpb    = (const float*)d_in[5];
    const float* proj_w = (const float*)d_in[6];
    const float* proj_b = (const float*)d_in[7];
    const float* ln2_g  = (const float*)d_in[8];
    const float* ln2_b  = (const float*)d_in[9];
    const float* fc1_w  = (const float*)d_in[10];
    const float* fc1_b  = (const float*)d_in[11];
    const float* fc2_w  = (const float*)d_in[12];
    const float* fc2_b  = (const float*)d_in[13];
    float* out = (float*)d_out;

    void* p;
    cudaGetSymbolAddress(&p, g_xw);   __nv_bfloat16* xw   = (__nv_bfloat16*)p;
    cudaGetSymbolAddress(&p, g_qkv);  __nv_bfloat16* qkvb = (__nv_bfloat16*)p;
    cudaGetSymbolAddress(&p, g_att);  __nv_bfloat16* att  = (__nv_bfloat16*)p;
    cudaGetSymbolAddress(&p, g_xres); float*         xres = (float*)p;
    cudaGetSymbolAddress(&p, g_mlp);  __nv_bfloat16* mlp  = (__nv_bfloat16*)p;
    cudaGetSymbolAddress(&p, g_wq);   __nv_bfloat16* wq = (__nv_bfloat16*)p;
    cudaGetSymbolAddress(&p, g_wp);   __nv_bfloat16* wp = (__nv_bfloat16*)p;
    cudaGetSymbolAddress(&p, g_w1);   __nv_bfloat16* w1 = (__nv_bfloat16*)p;
    cudaGetSymbolAddress(&p, g_w2);   __nv_bfloat16* w2 = (__nv_bfloat16*)p;

    static int attn_smem_set = 0;
    if (!attn_smem_set) {
        cudaFuncSetAttribute(attn_kernel, cudaFuncAttributeMaxDynamicSharedMemorySize,
                             ATTN_SMEM);
        attn_smem_set = 1;
    }

    // weight conversion (bf16), single launch
    f2bf_all<<<192, 256>>>(qkv_w, wq, 384 * 128, proj_w, wp, 128 * 128,
                           fc1_w, w1, 512 * 128, fc2_w, w2, 128 * 512);

    const int LN_BLOCKS = (TTOK * 32) / 256;  // 25088

    // 1. LN1 + shift + window partition (bf16 out)
    ln_kernel<true><<<LN_BLOCKS, 256>>>(x, ln1_g, ln1_b, xw);
    // 2. QKV projection: (T,128) @ (384,128)^T  [HMMA, cp.async pipelined]
    hgemm<0, false><<<dim3(3, 1568), 256>>>(xw, wq, qkv_b, nullptr, qkvb,
                                            TTOK, 384, 128);
    // 3. Windowed attention (HMMA, one block per window)
    attn_kernel<<<4096, 256, ATTN_SMEM>>>(qkvb, rpb, att);
    // 4. proj + window-reverse/unshift gather + residual (fp32 out)
    hgemm<2, true><<<dim3(1, 1568), 256>>>(att, wp, proj_b, x, xres,
                                           TTOK, 128, 128);
    // 5. LN2 (bf16 out)
    ln_kernel<false><<<LN_BLOCKS, 256>>>(xres, ln2_g, ln2_b, xw);
    // 6. fc1 + exact GELU (bf16 out)
    hgemm<1, false><<<dim3(4, 1568), 256>>>(xw, w1, fc1_b, nullptr, mlp,
                                            TTOK, 512, 128);
    // 7. fc2 + residual -> output (fp32)
    hgemm<2, false><<<dim3(1, 1568), 256>>>(mlp, w2, fc2_b, xres, out,
                                            TTOK, 128, 512);
}